// round 14
// baseline (speedup 1.0000x reference)
#include <cuda_runtime.h>
#include <math.h>

#define TSEQ 500
#define BATCH 512

typedef unsigned long long u64;

__device__ __forceinline__ void ffma2(u64& d, u64 a, u64 b, u64 c) {
    asm("fma.rn.f32x2 %0, %1, %2, %3;" : "=l"(d) : "l"(a), "l"(b), "l"(c));
}
__device__ __forceinline__ u64 fmul2(u64 a, u64 b) {
    u64 d; asm("mul.rn.f32x2 %0, %1, %2;" : "=l"(d) : "l"(a), "l"(b)); return d;
}
__device__ __forceinline__ u64 fadd2(u64 a, u64 b) {
    u64 d; asm("add.rn.f32x2 %0, %1, %2;" : "=l"(d) : "l"(a), "l"(b)); return d;
}
__device__ __forceinline__ float2 up2(u64 v) {
    float2 f; asm("mov.b64 {%0,%1}, %2;" : "=f"(f.x), "=f"(f.y) : "l"(v)); return f;
}
__device__ __forceinline__ u64 pk2(float x, float y) {
    u64 v; asm("mov.b64 %0, {%1,%2};" : "=l"(v) : "f"(x), "f"(y)); return v;
}

// ONE WARP PER BATCH. lane = rg*8 + cg; rg in [0,4): rows 16rg..16rg+15;
// cg in [0,8): cols 8cg..8cg+7. Thread owns P[16][8] as P2[16][4] packed f32x2.
// mu col strip (8 floats) replicated in registers across the 4 rg groups.
// Sequential scalar measurement updates (K=1), fully warp-local:
// 14-shfl reduce-scatter for v, STS.64 + __syncwarp + LDS strips, no barriers.

__global__ void __launch_bounds__(128, 1)
akf_main(const float* __restrict__ ext, const float* __restrict__ obs,
         const float* __restrict__ mu0, const float* __restrict__ sg0,
         const float* __restrict__ lsig, const float* __restrict__ Bm,
         const float* __restrict__ Hm, const float* __restrict__ ldel,
         float* __restrict__ out)
{
    __shared__ __align__(16) float sh_H[4096];
    __shared__ __align__(16) float sh_B[2048];
    __shared__ __align__(16) float sh_V[4][64];
    __shared__ __align__(16) float sh_u[4][32];
    __shared__ float sh_r[64], sh_q[64];

    const int tid  = threadIdx.x;
    const int w    = tid >> 5;
    const int lane = tid & 31;
    const int b    = (blockIdx.x << 2) | w;
    const int rg   = lane >> 3;
    const int cg   = lane & 7;
    const int r0   = rg << 4;      // first of my 16 rows
    const int c0   = cg << 3;      // first of my 8 cols
    const bool diag  = ((cg >> 1) == rg);
    const int  dbase = (cg & 1) << 3;   // local row offset of diag run
    const bool bb2 = cg & 4, bb1 = cg & 2, bb0 = cg & 1;

    for (int i = tid; i < 4096; i += 128) sh_H[i] = Hm[i];
    for (int i = tid; i < 2048; i += 128) sh_B[i] = Bm[i];
    if (tid < 64) {
        float e = expf(ldel[tid]); sh_r[tid] = e * e;
        float f = expf(lsig[tid]); sh_q[tid] = f * f;
    }

    u64 P2[16][4];
    #pragma unroll
    for (int a = 0; a < 16; ++a)
        #pragma unroll
        for (int m = 0; m < 4; ++m) P2[a][m] = 0ull;

    float* outmu = out;
    float* outls = out + (size_t)TSEQ * BATCH * 64;

    // mu col strip (registers, replicated across rg)
    u64 muc2[4];
    {
        const float* mp = &mu0[b * 64 + c0];
        #pragma unroll
        for (int p = 0; p < 4; ++p) muc2[p] = pk2(mp[2 * p], mp[2 * p + 1]);
    }
    if (diag) {
        #pragma unroll
        for (int j = 0; j < 8; ++j) {
            float s0v = sg0[b * 64 + c0 + j];
            float2 e = up2(P2[dbase + j][j >> 1]);
            if (j & 1) e.y = s0v * s0v; else e.x = s0v * s0v;
            P2[dbase + j][j >> 1] = pk2(e.x, e.y);
        }
    }
    if (rg == 0) {
        #pragma unroll
        for (int j = 0; j < 8; ++j) {
            outmu[b * 64 + c0 + j] = mu0[b * 64 + c0 + j];
            outls[b * 64 + c0 + j] = logf(sg0[b * 64 + c0 + j]);
        }
    }
    __syncthreads();   // sh_H / sh_B / sh_r / sh_q ready; warps independent after

    for (int t = 1; t < TSEQ; ++t) {
        // ---- step inputs: y into registers, u into warp smem ----
        float2 y2 = *(const float2*)&obs[((size_t)t * BATCH + b) * 64 + 2 * lane];
        sh_u[w][lane] = ext[((size_t)(t - 1) * BATCH + b) * 32 + lane];
        __syncwarp();

        // ---- predict: muc += (B u) for my 8 cols ; P += diag(q) ----
        {
            u64 uu[16];
            const ulonglong2* up = (const ulonglong2*)&sh_u[w][0];
            #pragma unroll
            for (int m = 0; m < 8; ++m) { ulonglong2 v = up[m]; uu[2*m] = v.x; uu[2*m+1] = v.y; }
            #pragma unroll
            for (int p = 0; p < 4; ++p) {
                float d[2];
                #pragma unroll
                for (int e = 0; e < 2; ++e) {
                    const ulonglong2* Bp = (const ulonglong2*)&sh_B[(c0 + 2*p + e) * 32];
                    u64 acc = 0ull;
                    #pragma unroll
                    for (int m = 0; m < 8; ++m) {
                        ulonglong2 bb = Bp[m];
                        ffma2(acc, bb.x, uu[2*m], acc);
                        ffma2(acc, bb.y, uu[2*m+1], acc);
                    }
                    float2 f = up2(acc); d[e] = f.x + f.y;
                }
                muc2[p] = fadd2(muc2[p], pk2(d[0], d[1]));
            }
        }
        if (diag) {
            #pragma unroll
            for (int j = 0; j < 8; ++j) {
                float qv = sh_q[c0 + j];
                float2 e = up2(P2[dbase + j][j >> 1]);
                if (j & 1) e.y += qv; else e.x += qv;
                P2[dbase + j][j >> 1] = pk2(e.x, e.y);
            }
        }

        // ---- 64 sequential scalar measurement updates (warp-local) ----
        #pragma unroll 1
        for (int i = 0; i < 64; ++i) {
            const ulonglong2* hp = (const ulonglong2*)&sh_H[(i << 6) + c0];
            ulonglong2 ha = hp[0], hb = hp[1];
            u64 h2[4] = {ha.x, ha.y, hb.x, hb.y};

            // v partials over 16 owned rows
            float vp[16];
            #pragma unroll
            for (int a = 0; a < 16; ++a) {
                u64 acc = 0ull;
                ffma2(acc, P2[a][0], h2[0], acc);
                ffma2(acc, P2[a][1], h2[1], acc);
                ffma2(acc, P2[a][2], h2[2], acc);
                ffma2(acc, P2[a][3], h2[3], acc);
                float2 f = up2(acc);
                vp[a] = f.x + f.y;
            }
            // reduce-scatter 16 values over the 8-lane octet (14 shuffles)
            float r8[8];
            #pragma unroll
            for (int m = 0; m < 8; ++m) {
                float keep = bb2 ? vp[m + 8] : vp[m];
                float send = bb2 ? vp[m]     : vp[m + 8];
                r8[m] = keep + __shfl_xor_sync(0xffffffffu, send, 4);
            }
            float r4[4];
            #pragma unroll
            for (int m = 0; m < 4; ++m) {
                float keep = bb1 ? r8[m + 4] : r8[m];
                float send = bb1 ? r8[m]     : r8[m + 4];
                r4[m] = keep + __shfl_xor_sync(0xffffffffu, send, 2);
            }
            float v0, v1;
            {
                float keep0 = bb0 ? r4[2] : r4[0];
                float send0 = bb0 ? r4[0] : r4[2];
                float keep1 = bb0 ? r4[3] : r4[1];
                float send1 = bb0 ? r4[1] : r4[3];
                v0 = keep0 + __shfl_xor_sync(0xffffffffu, send0, 1);
                v1 = keep1 + __shfl_xor_sync(0xffffffffu, send1, 1);
            }
            // lane holds v[16rg + 2cg + {0,1}]
            *(float2*)&sh_V[w][r0 + 2 * cg] = make_float2(v0, v1);
            __syncwarp();

            // v col strip (packed) + v row strip
            u64 vc2[4];
            {
                const ulonglong2* vq = (const ulonglong2*)&sh_V[w][c0];
                ulonglong2 va = vq[0], vb = vq[1];
                vc2[0] = va.x; vc2[1] = va.y; vc2[2] = vb.x; vc2[3] = vb.y;
            }
            float vr[16];
            {
                float4 q0 = *(const float4*)&sh_V[w][r0];
                float4 q1 = *(const float4*)&sh_V[w][r0 + 4];
                float4 q2 = *(const float4*)&sh_V[w][r0 + 8];
                float4 q3 = *(const float4*)&sh_V[w][r0 + 12];
                vr[0]=q0.x; vr[1]=q0.y; vr[2]=q0.z; vr[3]=q0.w;
                vr[4]=q1.x; vr[5]=q1.y; vr[6]=q1.z; vr[7]=q1.w;
                vr[8]=q2.x; vr[9]=q2.y; vr[10]=q2.z; vr[11]=q2.w;
                vr[12]=q3.x; vr[13]=q3.y; vr[14]=q3.z; vr[15]=q3.w;
            }

            // s = h.v ; z = h.mu (octet-local dots, 3+3 shuffles)
            u64 sa = 0ull, za = 0ull;
            #pragma unroll
            for (int m = 0; m < 4; ++m) {
                ffma2(sa, h2[m], vc2[m], sa);
                ffma2(za, h2[m], muc2[m], za);
            }
            float2 sf = up2(sa), zf = up2(za);
            float sp = sf.x + sf.y, zp = zf.x + zf.y;
            sp += __shfl_xor_sync(0xffffffffu, sp, 1);
            zp += __shfl_xor_sync(0xffffffffu, zp, 1);
            sp += __shfl_xor_sync(0xffffffffu, sp, 2);
            zp += __shfl_xor_sync(0xffffffffu, zp, 2);
            sp += __shfl_xor_sync(0xffffffffu, sp, 4);
            zp += __shfl_xor_sync(0xffffffffu, zp, 4);

            float rs = __fdividef(1.0f, sp + sh_r[i]);
            float yi = __shfl_sync(0xffffffffu, (i & 1) ? y2.y : y2.x, i >> 1);
            float coef = (yi - zp) * rs;

            // mu += coef * v (register col strip; identical in all rg copies)
            {
                u64 c2 = pk2(coef, coef);
                #pragma unroll
                for (int m = 0; m < 4; ++m) ffma2(muc2[m], c2, vc2[m], muc2[m]);
            }
            // rank-1: P -= rs * v v^T on owned tile
            {
                u64 nrs = pk2(-rs, -rs);
                u64 vcs2[4];
                #pragma unroll
                for (int m = 0; m < 4; ++m) vcs2[m] = fmul2(vc2[m], nrs);
                #pragma unroll
                for (int a = 0; a < 16; ++a) {
                    u64 g = pk2(vr[a], vr[a]);
                    ffma2(P2[a][0], g, vcs2[0], P2[a][0]);
                    ffma2(P2[a][1], g, vcs2[1], P2[a][1]);
                    ffma2(P2[a][2], g, vcs2[2], P2[a][2]);
                    ffma2(P2[a][3], g, vcs2[3], P2[a][3]);
                }
            }
        }

        // ---- outputs (no sync needed; all state warp/thread-local) ----
        if (rg == 0) {
            float2 m0f = up2(muc2[0]), m1f = up2(muc2[1]);
            float2 m2f = up2(muc2[2]), m3f = up2(muc2[3]);
            float* op = &outmu[((size_t)t * BATCH + b) * 64 + c0];
            *(float4*)op       = make_float4(m0f.x, m0f.y, m1f.x, m1f.y);
            *(float4*)(op + 4) = make_float4(m2f.x, m2f.y, m3f.x, m3f.y);
        }
        if (diag) {
            #pragma unroll
            for (int j = 0; j < 8; ++j) {
                float2 e = up2(P2[dbase + j][j >> 1]);
                float dv = (j & 1) ? e.y : e.x;
                outls[((size_t)t * BATCH + b) * 64 + c0 + j] = 0.5f * logf(dv);
            }
        }
    }
}

extern "C" void kernel_launch(void* const* d_in, const int* in_sizes, int n_in,
                              void* d_out, int out_size) {
    const float* ext  = (const float*)d_in[0];   // (500, 512, 32)
    const float* obs  = (const float*)d_in[1];   // (500, 512, 64)
    const float* mu0  = (const float*)d_in[2];   // (512, 64)
    const float* sg0  = (const float*)d_in[3];   // (512, 64)
    const float* lsig = (const float*)d_in[4];   // (64,)
    const float* Bm   = (const float*)d_in[5];   // (64, 32)
    const float* H    = (const float*)d_in[6];   // (64, 64)
    const float* ldel = (const float*)d_in[7];   // (64,)
    float* out = (float*)d_out;

    akf_main<<<BATCH / 4, 128>>>(ext, obs, mu0, sg0, lsig, Bm, H, ldel, out);
}